// round 1
// baseline (speedup 1.0000x reference)
#include <cuda_runtime.h>
#include <math.h>

// Problem dims (fixed by the reference)
#define Bq 4
#define Sq 2048
#define Eq 1024
#define Hn 16
#define Dd 64
#define BSq (Bq*Sq)      // 8192 rows
#define FEq (4*Eq)       // 4096 MLP hidden

// ---------------- scratch (no allocations allowed) ----------------
__device__ float g_h[(size_t)BSq*Eq];     // ln1 output (also attn residual)
__device__ float g_q[(size_t)BSq*Eq];
__device__ float g_k[(size_t)BSq*Eq];
__device__ float g_v[(size_t)BSq*Eq];
__device__ float g_attn[(size_t)BSq*Eq];
__device__ float g_t[(size_t)BSq*Eq];     // ln2 output
__device__ float g_u[(size_t)BSq*FEq];    // fc+gelu output
__device__ unsigned char g_mask[(size_t)Sq*Sq];

// ---------------- mask canonicalization ----------------
// The reference mask is bool[S,S]. Depending on harness dtype handling it may
// arrive as 1-byte bool or as int32. Discriminate via byte offset 2048:
// mask[1,0] == True -> byte 2048 == 1 in byte layout; in int32 layout byte
// 2048 belongs to element 512 of row 0 (False) -> 0.
__global__ void mask_convert_kernel(const unsigned char* __restrict__ m) {
    size_t i = (size_t)blockIdx.x * blockDim.x + threadIdx.x;
    if (i >= (size_t)Sq * Sq) return;
    bool is_byte_layout = (m[2048] != 0);
    unsigned char val;
    if (is_byte_layout) {
        val = (m[i] != 0) ? 1 : 0;
    } else {
        val = (((const int*)m)[i] != 0) ? 1 : 0;
    }
    g_mask[i] = val;
}

// ---------------- layernorm ----------------
__global__ void ln_kernel(const float* __restrict__ x, const float* __restrict__ g,
                          const float* __restrict__ b, float* __restrict__ out) {
    int row = blockIdx.x;
    const float* xr = x + (size_t)row * Eq;
    float s = 0.f, s2 = 0.f;
    for (int i = threadIdx.x; i < Eq; i += blockDim.x) {
        float v = xr[i];
        s += v; s2 += v * v;
    }
    __shared__ float sh[64];
    #pragma unroll
    for (int o = 16; o; o >>= 1) {
        s  += __shfl_xor_sync(0xffffffffu, s,  o);
        s2 += __shfl_xor_sync(0xffffffffu, s2, o);
    }
    int wid = threadIdx.x >> 5, nl = threadIdx.x & 31;
    if (nl == 0) { sh[wid] = s; sh[32 + wid] = s2; }
    __syncthreads();
    if (wid == 0) {
        int nw = blockDim.x >> 5;
        s  = (nl < nw) ? sh[nl] : 0.f;
        s2 = (nl < nw) ? sh[32 + nl] : 0.f;
        #pragma unroll
        for (int o = 16; o; o >>= 1) {
            s  += __shfl_xor_sync(0xffffffffu, s,  o);
            s2 += __shfl_xor_sync(0xffffffffu, s2, o);
        }
        if (nl == 0) { sh[0] = s; sh[1] = s2; }
    }
    __syncthreads();
    float mean = sh[0] * (1.f / Eq);
    float var  = sh[1] * (1.f / Eq) - mean * mean;
    float rstd = rsqrtf(var + 1e-5f);
    float* orow = out + (size_t)row * Eq;
    for (int i = threadIdx.x; i < Eq; i += blockDim.x) {
        orow[i] = (xr[i] - mean) * rstd * g[i] + b[i];
    }
}

// ---------------- GEMM: C[M,N] = epi( A[M,K] @ B[N,K]^T ) ----------------
// epilogue: v = alpha*(dot + bias[n]); if gelu: v = gelu(v); if res: v += res[m,n]
__global__ __launch_bounds__(256)
void gemm_abt_kernel(const float* __restrict__ A, const float* __restrict__ Bm,
                     const float* __restrict__ bias, const float* __restrict__ res,
                     float* __restrict__ C, int M, int N, int K,
                     float alpha, int do_gelu)
{
    __shared__ float As[16][68];
    __shared__ float Bs[16][68];
    int tid = threadIdx.x;
    int bm = blockIdx.y * 64, bn = blockIdx.x * 64;
    int tx = tid & 15, ty = tid >> 4;
    float acc[4][4];
    #pragma unroll
    for (int i = 0; i < 4; i++)
        #pragma unroll
        for (int j = 0; j < 4; j++) acc[i][j] = 0.f;

    int lr = tid >> 2;          // 0..63 tile row
    int lc = (tid & 3) * 4;     // 0,4,8,12 within K-tile
    const float* Ap = A + (size_t)(bm + lr) * K + lc;
    const float* Bp = Bm + (size_t)(bn + lr) * K + lc;

    for (int k0 = 0; k0 < K; k0 += 16) {
        float4 a4 = *(const float4*)(Ap + k0);
        float4 b4 = *(const float4*)(Bp + k0);
        As[lc + 0][lr] = a4.x; As[lc + 1][lr] = a4.y;
        As[lc + 2][lr] = a4.z; As[lc + 3][lr] = a4.w;
        Bs[lc + 0][lr] = b4.x; Bs[lc + 1][lr] = b4.y;
        Bs[lc + 2][lr] = b4.z; Bs[lc + 3][lr] = b4.w;
        __syncthreads();
        #pragma unroll
        for (int kk = 0; kk < 16; kk++) {
            float ar[4], br[4];
            #pragma unroll
            for (int i = 0; i < 4; i++) ar[i] = As[kk][ty * 4 + i];
            #pragma unroll
            for (int j = 0; j < 4; j++) br[j] = Bs[kk][tx * 4 + j];
            #pragma unroll
            for (int i = 0; i < 4; i++)
                #pragma unroll
                for (int j = 0; j < 4; j++)
                    acc[i][j] = fmaf(ar[i], br[j], acc[i][j]);
        }
        __syncthreads();
    }

    const float cgelu = 0.7978845608028654f;
    #pragma unroll
    for (int i = 0; i < 4; i++) {
        int r = bm + ty * 4 + i;
        #pragma unroll
        for (int j = 0; j < 4; j++) {
            int c = bn + tx * 4 + j;
            float v = (acc[i][j] + bias[c]) * alpha;
            if (do_gelu) {
                float x = v;
                float inner = cgelu * (x + 0.044715f * x * x * x);
                v = 0.5f * x * (1.f + tanhf(inner));
            }
            if (res) v += res[(size_t)r * N + c];
            C[(size_t)r * N + c] = v;
        }
    }
}

// ---------------- sparse causal attention (flash-style, warp per query) ----
__global__ void attn_kernel(const float* __restrict__ q, const float* __restrict__ k,
                            const float* __restrict__ v, float* __restrict__ out)
{
    int warp = threadIdx.x >> 5;
    int lane = threadIdx.x & 31;
    int qi = blockIdx.x * (blockDim.x >> 5) + warp;
    int h = blockIdx.y, b = blockIdx.z;
    if (qi >= Sq) return;

    size_t qoff = (((size_t)b * Sq + qi) * Hn + h) * Dd + lane * 2;
    float2 q2 = *(const float2*)(q + qoff);
    const unsigned char* mrow = g_mask + (size_t)qi * Sq;
    size_t kbase = (((size_t)b * Sq) * Hn + h) * Dd + lane * 2;

    float m = -1e30f, l = 0.f;
    float accx = 0.f, accy = 0.f;

    for (int key = 0; key <= qi; key++) {
        if (mrow[key]) {
            size_t off = kbase + (size_t)key * (Hn * Dd);
            float2 kk = *(const float2*)(k + off);
            float part = q2.x * kk.x + q2.y * kk.y;
            #pragma unroll
            for (int o = 16; o; o >>= 1)
                part += __shfl_xor_sync(0xffffffffu, part, o);
            float nm = fmaxf(m, part);
            float sc = __expf(m - nm);
            float p  = __expf(part - nm);
            l = l * sc + p;
            float2 vv = *(const float2*)(v + off);
            accx = accx * sc + p * vv.x;
            accy = accy * sc + p * vv.y;
            m = nm;
        }
    }
    float inv = 1.f / l;
    *(float2*)(out + qoff) = make_float2(accx * inv, accy * inv);
}

// ---------------- host ----------------
extern "C" void kernel_launch(void* const* d_in, const int* in_sizes, int n_in,
                              void* d_out, int out_size) {
    const float* x      = (const float*)d_in[0];
    const float* ln1_g  = (const float*)d_in[1];
    const float* ln1_b  = (const float*)d_in[2];
    const float* ln2_g  = (const float*)d_in[3];
    const float* ln2_b  = (const float*)d_in[4];
    const float* wq     = (const float*)d_in[5];
    const float* bq     = (const float*)d_in[6];
    const float* wk     = (const float*)d_in[7];
    const float* bk     = (const float*)d_in[8];
    const float* wv     = (const float*)d_in[9];
    const float* bv     = (const float*)d_in[10];
    const float* wo     = (const float*)d_in[11];
    const float* bo     = (const float*)d_in[12];
    const float* w_fc   = (const float*)d_in[13];
    const float* b_fc   = (const float*)d_in[14];
    const float* w_proj = (const float*)d_in[15];
    const float* b_proj = (const float*)d_in[16];
    const unsigned char* mask = (const unsigned char*)d_in[17];
    float* out = (float*)d_out;

    float *h, *qp, *kp, *vp, *attn, *t, *u;
    cudaGetSymbolAddress((void**)&h,    g_h);
    cudaGetSymbolAddress((void**)&qp,   g_q);
    cudaGetSymbolAddress((void**)&kp,   g_k);
    cudaGetSymbolAddress((void**)&vp,   g_v);
    cudaGetSymbolAddress((void**)&attn, g_attn);
    cudaGetSymbolAddress((void**)&t,    g_t);
    cudaGetSymbolAddress((void**)&u,    g_u);

    const float scale = 0.125f; // D^-0.5, D=64

    // mask -> canonical uint8
    {
        size_t n = (size_t)Sq * Sq;
        int threads = 256;
        int blocks = (int)((n + threads - 1) / threads);
        mask_convert_kernel<<<blocks, threads>>>(mask);
    }

    // h = ln1(x)
    ln_kernel<<<BSq, 256>>>(x, ln1_g, ln1_b, h);

    // q,k,v projections
    dim3 gEE(Eq / 64, BSq / 64);
    gemm_abt_kernel<<<gEE, 256>>>(h, wq, bq, nullptr, qp, BSq, Eq, Eq, scale, 0);
    gemm_abt_kernel<<<gEE, 256>>>(h, wk, bk, nullptr, kp, BSq, Eq, Eq, 1.f, 0);
    gemm_abt_kernel<<<gEE, 256>>>(h, wv, bv, nullptr, vp, BSq, Eq, Eq, 1.f, 0);

    // sparse attention
    attn_kernel<<<dim3(Sq / 4, Hn, Bq), 128>>>(qp, kp, vp, attn);

    // out = h + attn @ wo^T + bo
    gemm_abt_kernel<<<gEE, 256>>>(attn, wo, bo, h, out, BSq, Eq, Eq, 1.f, 0);

    // t = ln2(out)
    ln_kernel<<<BSq, 256>>>(out, ln2_g, ln2_b, t);

    // u = gelu(t @ w_fc^T + b_fc)
    dim3 gFC(FEq / 64, BSq / 64);
    gemm_abt_kernel<<<gFC, 256>>>(t, w_fc, b_fc, nullptr, u, BSq, FEq, Eq, 1.f, 1);

    // out += u @ w_proj^T + b_proj
    gemm_abt_kernel<<<gEE, 256>>>(u, w_proj, b_proj, out, out, BSq, Eq, FEq, 1.f, 0);
}

// round 2
// speedup vs baseline: 1.9533x; 1.9533x over previous
#include <cuda_runtime.h>
#include <math.h>
#include <stdint.h>

// Problem dims (fixed by the reference)
#define Bq 4
#define Sq 2048
#define Eq 1024
#define Hn 16
#define Dd 64
#define BSq (Bq*Sq)      // 8192 rows
#define FEq (4*Eq)       // 4096 MLP hidden
#define IDXS 1024        // max live keys per query row (actual max ~657)

// ---------------- scratch (no allocations allowed) ----------------
__device__ float g_h [(size_t)BSq*Eq];    // ln1 fp32 (residual)
__device__ float g_hr[(size_t)BSq*Eq];    // ln1 tf32-rounded (GEMM input)
__device__ float g_q [(size_t)BSq*Eq];
__device__ float g_k [(size_t)BSq*Eq];
__device__ float g_v [(size_t)BSq*Eq];
__device__ float g_attn[(size_t)BSq*Eq];  // tf32-rounded attention output
__device__ float g_t [(size_t)BSq*Eq];    // ln2 tf32-rounded
__device__ float g_u [(size_t)BSq*FEq];   // gelu output, tf32-rounded
__device__ float g_w [(size_t)12*1024*1024]; // rounded weights
__device__ unsigned char g_mask[(size_t)Sq*Sq];
__device__ int g_idx[(size_t)Sq*IDXS];
__device__ int g_cnt[Sq];

// ---------------- helpers ----------------
__device__ __forceinline__ float f2tf32(float x) {
    uint32_t r; asm("cvt.rna.tf32.f32 %0, %1;" : "=r"(r) : "f"(x));
    return __uint_as_float(r);
}
__device__ __forceinline__ float fast_ex2(float x) {
    float y; asm("ex2.approx.f32 %0, %1;" : "=f"(y) : "f"(x)); return y;
}
__device__ __forceinline__ float fast_tanh(float x) {
    float y; asm("tanh.approx.f32 %0, %1;" : "=f"(y) : "f"(x)); return y;
}
__device__ __forceinline__ void cpa16(uint32_t dst, const void* src) {
    asm volatile("cp.async.ca.shared.global [%0], [%1], 16;" :: "r"(dst), "l"(src));
}
template<int N> __device__ __forceinline__ void cp_wait() {
    asm volatile("cp.async.wait_group %0;" :: "n"(N) : "memory");
}
__device__ __forceinline__ void cp_commit() {
    asm volatile("cp.async.commit_group;" ::: "memory");
}
__device__ __forceinline__ void mma1688(float* c, uint32_t a0, uint32_t a1,
                                        uint32_t a2, uint32_t a3,
                                        uint32_t b0, uint32_t b1) {
    asm volatile(
        "mma.sync.aligned.m16n8k8.row.col.f32.tf32.tf32.f32 "
        "{%0,%1,%2,%3}, {%4,%5,%6,%7}, {%8,%9}, {%0,%1,%2,%3};"
        : "+f"(c[0]), "+f"(c[1]), "+f"(c[2]), "+f"(c[3])
        : "r"(a0), "r"(a1), "r"(a2), "r"(a3), "r"(b0), "r"(b1));
}

// ---------------- mask canonicalization ----------------
__global__ void mask_convert_kernel(const unsigned char* __restrict__ m) {
    size_t i = (size_t)blockIdx.x * blockDim.x + threadIdx.x;
    if (i >= (size_t)Sq * Sq) return;
    bool is_byte_layout = (m[2048] != 0);
    unsigned char val;
    if (is_byte_layout) val = (m[i] != 0) ? 1 : 0;
    else                val = (((const int*)m)[i] != 0) ? 1 : 0;
    g_mask[i] = val;
}

// ---------------- per-row live-key index lists ----------------
__global__ void build_idx_kernel() {
    int qi = blockIdx.x * blockDim.x + threadIdx.x;
    if (qi >= Sq) return;
    const unsigned char* mr = g_mask + (size_t)qi * Sq;
    int c = 0;
    for (int j = 0; j <= qi; j++)
        if (mr[j]) g_idx[(size_t)qi * IDXS + c++] = j;
    g_cnt[qi] = c;
}

// ---------------- tf32 rounding of weights ----------------
__global__ void round_kernel(const float* __restrict__ in, float* __restrict__ out, int n4) {
    int i = blockIdx.x * blockDim.x + threadIdx.x;
    if (i >= n4) return;
    float4 v = ((const float4*)in)[i];
    v.x = f2tf32(v.x); v.y = f2tf32(v.y); v.z = f2tf32(v.z); v.w = f2tf32(v.w);
    ((float4*)out)[i] = v;
}

// ---------------- layernorm (dual output: exact + tf32-rounded) ----------------
__global__ void ln_kernel(const float* __restrict__ x, const float* __restrict__ g,
                          const float* __restrict__ b, float* __restrict__ out,
                          float* __restrict__ out_r) {
    int row = blockIdx.x;
    const float* xr = x + (size_t)row * Eq;
    float s = 0.f, s2 = 0.f;
    for (int i = threadIdx.x; i < Eq; i += blockDim.x) {
        float v = xr[i];
        s += v; s2 += v * v;
    }
    __shared__ float sh[64];
    #pragma unroll
    for (int o = 16; o; o >>= 1) {
        s  += __shfl_xor_sync(0xffffffffu, s,  o);
        s2 += __shfl_xor_sync(0xffffffffu, s2, o);
    }
    int wid = threadIdx.x >> 5, nl = threadIdx.x & 31;
    if (nl == 0) { sh[wid] = s; sh[32 + wid] = s2; }
    __syncthreads();
    if (wid == 0) {
        int nw = blockDim.x >> 5;
        s  = (nl < nw) ? sh[nl] : 0.f;
        s2 = (nl < nw) ? sh[32 + nl] : 0.f;
        #pragma unroll
        for (int o = 16; o; o >>= 1) {
            s  += __shfl_xor_sync(0xffffffffu, s,  o);
            s2 += __shfl_xor_sync(0xffffffffu, s2, o);
        }
        if (nl == 0) { sh[0] = s; sh[1] = s2; }
    }
    __syncthreads();
    float mean = sh[0] * (1.f / Eq);
    float var  = sh[1] * (1.f / Eq) - mean * mean;
    float rstd = rsqrtf(var + 1e-5f);
    for (int i = threadIdx.x; i < Eq; i += blockDim.x) {
        float v = (xr[i] - mean) * rstd * g[i] + b[i];
        if (out)   out[(size_t)row * Eq + i]   = v;
        if (out_r) out_r[(size_t)row * Eq + i] = f2tf32(v);
    }
}

// ---------------- tf32 tensor-core GEMM: C = epi( A[M,K] @ B[N,K]^T ) ----------------
// A, B must be pre-rounded to tf32. BM=BN=128, BK=32, 256 threads, cp.async 2-stage.
#define SSTR 36
#define TILEF (128*SSTR)

__global__ __launch_bounds__(256, 2)
void gemm_tf32_kernel(const float* __restrict__ A, const float* __restrict__ Bmat,
                      const float* __restrict__ bias, const float* __restrict__ res,
                      float* __restrict__ C, int M, int N, int K,
                      float alpha, int do_gelu, int round_out)
{
    extern __shared__ float sm[];
    const uint32_t sbase = (uint32_t)__cvta_generic_to_shared(sm);

    int tid = threadIdx.x;
    int bm = blockIdx.y * 128, bn = blockIdx.x * 128;
    int warp = tid >> 5, lane = tid & 31;
    int g = lane >> 2, tig = lane & 3;
    int m0 = (warp >> 1) * 32, n0 = (warp & 1) * 64;

    // global-load mapping: 2 threads per row, 16 contiguous floats each
    int lrow = tid >> 1;
    int lcb  = (tid & 1) * 16;
    const float* Ag = A    + (size_t)(bm + lrow) * K + lcb;
    const float* Bg = Bmat + (size_t)(bn + lrow) * K + lcb;
    uint32_t sA_st = sbase + (uint32_t)(lrow * SSTR + lcb) * 4u;

    float acc[2][8][4];
    #pragma unroll
    for (int i = 0; i < 2; i++)
        #pragma unroll
        for (int j = 0; j < 8; j++)
            #pragma unroll
            for (int l = 0; l < 4; l++) acc[i][j][l] = 0.f;

    int T = K / 32;
    // prologue: issue tile 0 into stage 0
    {
        #pragma unroll
        for (int j = 0; j < 4; j++) {
            cpa16(sA_st + j * 16, Ag + j * 4);
            cpa16(sA_st + TILEF * 4 + j * 16, Bg + j * 4);
        }
        cp_commit();
    }

    for (int t = 0; t < T; t++) {
        if (t + 1 < T) {
            uint32_t dst = sA_st + (uint32_t)(((t + 1) & 1) * 2 * TILEF) * 4u;
            const float* ap = Ag + (t + 1) * 32;
            const float* bp = Bg + (t + 1) * 32;
            #pragma unroll
            for (int j = 0; j < 4; j++) {
                cpa16(dst + j * 16, ap + j * 4);
                cpa16(dst + TILEF * 4 + j * 16, bp + j * 4);
            }
            cp_commit();
            cp_wait<1>();
        } else {
            cp_wait<0>();
        }
        __syncthreads();

        const float* sA = sm + (t & 1) * 2 * TILEF;
        const float* sB = sA + TILEF;
        #pragma unroll
        for (int ks = 0; ks < 4; ks++) {
            int k = ks * 8;
            uint32_t bfr[8][2];
            #pragma unroll
            for (int nt = 0; nt < 8; nt++) {
                bfr[nt][0] = __float_as_uint(sB[(n0 + nt * 8 + g) * SSTR + k + tig]);
                bfr[nt][1] = __float_as_uint(sB[(n0 + nt * 8 + g) * SSTR + k + tig + 4]);
            }
            #pragma unroll
            for (int mt = 0; mt < 2; mt++) {
                int rbase = (m0 + mt * 16 + g) * SSTR + k;
                uint32_t a0 = __float_as_uint(sA[rbase + tig]);
                uint32_t a1 = __float_as_uint(sA[rbase + 8 * SSTR + tig]);
                uint32_t a2 = __float_as_uint(sA[rbase + tig + 4]);
                uint32_t a3 = __float_as_uint(sA[rbase + 8 * SSTR + tig + 4]);
                #pragma unroll
                for (int nt = 0; nt < 8; nt++)
                    mma1688(acc[mt][nt], a0, a1, a2, a3, bfr[nt][0], bfr[nt][1]);
            }
        }
        __syncthreads();
    }

    // epilogue
    const float cgelu = 0.7978845608028654f;
    #pragma unroll
    for (int mt = 0; mt < 2; mt++) {
        #pragma unroll
        for (int half = 0; half < 2; half++) {
            int r = bm + m0 + mt * 16 + g + half * 8;
            #pragma unroll
            for (int nt = 0; nt < 8; nt++) {
                int c = bn + n0 + nt * 8 + 2 * tig;
                float v0 = (acc[mt][nt][half * 2 + 0] + bias[c])     * alpha;
                float v1 = (acc[mt][nt][half * 2 + 1] + bias[c + 1]) * alpha;
                if (do_gelu) {
                    float i0 = cgelu * (v0 + 0.044715f * v0 * v0 * v0);
                    float i1 = cgelu * (v1 + 0.044715f * v1 * v1 * v1);
                    v0 = 0.5f * v0 * (1.f + fast_tanh(i0));
                    v1 = 0.5f * v1 * (1.f + fast_tanh(i1));
                }
                if (res) {
                    v0 += res[(size_t)r * N + c];
                    v1 += res[(size_t)r * N + c + 1];
                }
                if (round_out) { v0 = f2tf32(v0); v1 = f2tf32(v1); }
                *(float2*)(C + (size_t)r * N + c) = make_float2(v0, v1);
            }
        }
    }
}

// ---------------- sparse attention: warp/query, index-list driven ----------------
__global__ void attn_kernel(const float* __restrict__ q, const float* __restrict__ k,
                            const float* __restrict__ v, float* __restrict__ out)
{
    const float LOG2E = 1.4426950408889634f;
    int warp = threadIdx.x >> 5;
    int lane = threadIdx.x & 31;
    int qi = blockIdx.x * (blockDim.x >> 5) + warp;
    int h = blockIdx.y, b = blockIdx.z;
    if (qi >= Sq) return;

    size_t qoff = (((size_t)b * Sq + qi) * Hn + h) * Dd + lane * 2;
    float2 q2 = *(const float2*)(q + qoff);
    size_t kbase = (((size_t)b * Sq) * Hn + h) * Dd + lane * 2;

    int cnt = g_cnt[qi];
    const int* irow = g_idx + (size_t)qi * IDXS;

    float m = -1e30f, l = 0.f;
    float accx = 0.f, accy = 0.f;

    for (int i = 0; i < cnt; i++) {
        int key = irow[i];
        size_t off = kbase + (size_t)key * (Hn * Dd);
        float2 kk = *(const float2*)(k + off);
        float2 vv = *(const float2*)(v + off);
        float part = q2.x * kk.x + q2.y * kk.y;
        #pragma unroll
        for (int o = 16; o; o >>= 1)
            part += __shfl_xor_sync(0xffffffffu, part, o);
        if (part <= m) {                       // warp-uniform branch
            float p = fast_ex2((part - m) * LOG2E);
            l += p;
            accx += p * vv.x; accy += p * vv.y;
        } else {
            float sc = fast_ex2((m - part) * LOG2E);
            l = l * sc + 1.f;
            accx = accx * sc + vv.x; accy = accy * sc + vv.y;
            m = part;
        }
    }
    float inv = 1.f / l;
    *(float2*)(out + qoff) = make_float2(f2tf32(accx * inv), f2tf32(accy * inv));
}

// ---------------- host ----------------
extern "C" void kernel_launch(void* const* d_in, const int* in_sizes, int n_in,
                              void* d_out, int out_size) {
    const float* x      = (const float*)d_in[0];
    const float* ln1_g  = (const float*)d_in[1];
    const float* ln1_b  = (const float*)d_in[2];
    const float* ln2_g  = (const float*)d_in[3];
    const float* ln2_b  = (const float*)d_in[4];
    const float* wq     = (const float*)d_in[5];
    const float* bq     = (const float*)d_in[6];
    const float* wk     = (const float*)d_in[7];
    const float* bk     = (const float*)d_in[8];
    const float* wv     = (const float*)d_in[9];
    const float* bv     = (const float*)d_in[10];
    const float* wo     = (const float*)d_in[11];
    const float* bo     = (const float*)d_in[12];
    const float* w_fc   = (const float*)d_in[13];
    const float* b_fc   = (const float*)d_in[14];
    const float* w_proj = (const float*)d_in[15];
    const float* b_proj = (const float*)d_in[16];
    const unsigned char* mask = (const unsigned char*)d_in[17];
    float* out = (float*)d_out;

    float *h, *hr, *qp, *kp, *vp, *attn, *t, *u, *w;
    cudaGetSymbolAddress((void**)&h,    g_h);
    cudaGetSymbolAddress((void**)&hr,   g_hr);
    cudaGetSymbolAddress((void**)&qp,   g_q);
    cudaGetSymbolAddress((void**)&kp,   g_k);
    cudaGetSymbolAddress((void**)&vp,   g_v);
    cudaGetSymbolAddress((void**)&attn, g_attn);
    cudaGetSymbolAddress((void**)&t,    g_t);
    cudaGetSymbolAddress((void**)&u,    g_u);
    cudaGetSymbolAddress((void**)&w,    g_w);

    const size_t EE = (size_t)Eq * Eq;           // 1M
    float* wq_r = w;
    float* wk_r = w + EE;
    float* wv_r = w + 2 * EE;
    float* wo_r = w + 3 * EE;
    float* wfc_r = w + 4 * EE;                   // 4M floats
    float* wpr_r = w + 8 * EE;                   // 4M floats

    const int smem_bytes = 2 * 2 * TILEF * 4;    // 73728
    cudaFuncSetAttribute(gemm_tf32_kernel,
                         cudaFuncAttributeMaxDynamicSharedMemorySize, smem_bytes);

    // weights -> tf32-rounded copies
    {
        int thr = 256;
        int n4 = (int)(EE / 4);
        round_kernel<<<(n4 + thr - 1) / thr, thr>>>(wq, wq_r, n4);
        round_kernel<<<(n4 + thr - 1) / thr, thr>>>(wk, wk_r, n4);
        round_kernel<<<(n4 + thr - 1) / thr, thr>>>(wv, wv_r, n4);
        round_kernel<<<(n4 + thr - 1) / thr, thr>>>(wo, wo_r, n4);
        int n4f = (int)(4 * EE / 4);
        round_kernel<<<(n4f + thr - 1) / thr, thr>>>(w_fc,   wfc_r, n4f);
        round_kernel<<<(n4f + thr - 1) / thr, thr>>>(w_proj, wpr_r, n4f);
    }

    // mask -> canonical uint8, then index lists
    {
        size_t n = (size_t)Sq * Sq;
        mask_convert_kernel<<<(int)((n + 255) / 256), 256>>>(mask);
        build_idx_kernel<<<(Sq + 255) / 256, 256>>>();
    }

    const float scale = 0.125f; // D^-0.5

    // h = ln1(x) (exact + rounded)
    ln_kernel<<<BSq, 256>>>(x, ln1_g, ln1_b, h, hr);

    // q,k,v projections (tensor core)
    dim3 gEE(Eq / 128, BSq / 128);
    gemm_tf32_kernel<<<gEE, 256, smem_bytes>>>(hr, wq_r, bq, nullptr, qp, BSq, Eq, Eq, scale, 0, 0);
    gemm_tf32_kernel<<<gEE, 256, smem_bytes>>>(hr, wk_r, bk, nullptr, kp, BSq, Eq, Eq, 1.f, 0, 0);
    gemm_tf32_kernel<<<gEE, 256, smem_bytes>>>(hr, wv_r, bv, nullptr, vp, BSq, Eq, Eq, 1.f, 0, 0);

    // sparse attention
    attn_kernel<<<dim3(Sq / 4, Hn, Bq), 128>>>(qp, kp, vp, attn);

    // out = h + attn @ wo^T + bo
    gemm_tf32_kernel<<<gEE, 256, smem_bytes>>>(attn, wo_r, bo, h, out, BSq, Eq, Eq, 1.f, 0, 0);

    // t = ln2(out) (rounded only)
    ln_kernel<<<BSq, 256>>>(out, ln2_g, ln2_b, nullptr, t);

    // u = gelu(t @ w_fc^T + b_fc), rounded
    dim3 gFC(FEq / 128, BSq / 128);
    gemm_tf32_kernel<<<gFC, 256, smem_bytes>>>(t, wfc_r, b_fc, nullptr, u, BSq, FEq, Eq, 1.f, 1, 1);

    // out += u @ w_proj^T + b_proj
    gemm_tf32_kernel<<<gEE, 256, smem_bytes>>>(u, wpr_r, b_proj, out, out, BSq, Eq, FEq, 1.f, 0, 0);
}

// round 3
// speedup vs baseline: 3.4087x; 1.7451x over previous
#include <cuda_runtime.h>
#include <math.h>
#include <stdint.h>

// Problem dims (fixed by the reference)
#define Bq 4
#define Sq 2048
#define Eq 1024
#define Hn 16
#define Dd 64
#define BSq (Bq*Sq)      // 8192 rows
#define FEq (4*Eq)       // 4096 MLP hidden
#define QT 64            // query tile for attention
#define NT (Sq/QT)       // 32 tiles
#define IDXS_T 1024      // max union keys per tile (actual max ~750)

// ---------------- scratch (no allocations allowed) ----------------
__device__ float g_h [(size_t)BSq*Eq];    // ln1 fp32 (residual)
__device__ float g_hr[(size_t)BSq*Eq];    // ln1 tf32-rounded (GEMM input)
__device__ float g_q [(size_t)BSq*Eq];
__device__ float g_k [(size_t)BSq*Eq];
__device__ float g_v [(size_t)BSq*Eq];
__device__ float g_attn[(size_t)BSq*Eq];  // tf32-rounded attention output
__device__ float g_t [(size_t)BSq*Eq];    // ln2 tf32-rounded
__device__ float g_u [(size_t)BSq*FEq];   // gelu output, tf32-rounded
__device__ float g_w [(size_t)12*1024*1024]; // rounded weights
__device__ unsigned char g_mask[(size_t)Sq*Sq];
__device__ int g_tile_idx[(size_t)NT*IDXS_T];
__device__ unsigned long long g_tile_bits[(size_t)NT*IDXS_T];
__device__ int g_tile_cnt[NT];

// ---------------- helpers ----------------
__device__ __forceinline__ float f2tf32(float x) {
    uint32_t r; asm("cvt.rna.tf32.f32 %0, %1;" : "=r"(r) : "f"(x));
    return __uint_as_float(r);
}
__device__ __forceinline__ float fast_ex2(float x) {
    float y; asm("ex2.approx.f32 %0, %1;" : "=f"(y) : "f"(x)); return y;
}
__device__ __forceinline__ float fast_tanh(float x) {
    float y; asm("tanh.approx.f32 %0, %1;" : "=f"(y) : "f"(x)); return y;
}
__device__ __forceinline__ void cpa16(uint32_t dst, const void* src) {
    asm volatile("cp.async.ca.shared.global [%0], [%1], 16;" :: "r"(dst), "l"(src));
}
template<int N> __device__ __forceinline__ void cp_wait() {
    asm volatile("cp.async.wait_group %0;" :: "n"(N) : "memory");
}
__device__ __forceinline__ void cp_commit() {
    asm volatile("cp.async.commit_group;" ::: "memory");
}
__device__ __forceinline__ void mma1688(float* c, uint32_t a0, uint32_t a1,
                                        uint32_t a2, uint32_t a3,
                                        uint32_t b0, uint32_t b1) {
    asm volatile(
        "mma.sync.aligned.m16n8k8.row.col.f32.tf32.tf32.f32 "
        "{%0,%1,%2,%3}, {%4,%5,%6,%7}, {%8,%9}, {%0,%1,%2,%3};"
        : "+f"(c[0]), "+f"(c[1]), "+f"(c[2]), "+f"(c[3])
        : "r"(a0), "r"(a1), "r"(a2), "r"(a3), "r"(b0), "r"(b1));
}

// ---------------- fused tf32 rounding of all weights ----------------
// g_w layout (float4 units): wq[0,256K) wk[256K,512K) wv[512K,768K) wo[768K,1M)
// wfc[1M,2M) wproj[2M,3M)
__global__ void round_all_kernel(const float* __restrict__ wq, const float* __restrict__ wk,
                                 const float* __restrict__ wv, const float* __restrict__ wo,
                                 const float* __restrict__ wfc, const float* __restrict__ wpr,
                                 float* __restrict__ dst) {
    int i = blockIdx.x * blockDim.x + threadIdx.x;   // float4 index, total 3M
    const int Q1 = 256 * 1024;
    const float4* src;
    int off;
    if      (i <     Q1) { src = (const float4*)wq;  off = i; }
    else if (i < 2 * Q1) { src = (const float4*)wk;  off = i - Q1; }
    else if (i < 3 * Q1) { src = (const float4*)wv;  off = i - 2 * Q1; }
    else if (i < 4 * Q1) { src = (const float4*)wo;  off = i - 3 * Q1; }
    else if (i < 8 * Q1) { src = (const float4*)wfc; off = i - 4 * Q1; }
    else                 { src = (const float4*)wpr; off = i - 8 * Q1; }
    float4 v = src[off];
    v.x = f2tf32(v.x); v.y = f2tf32(v.y); v.z = f2tf32(v.z); v.w = f2tf32(v.w);
    ((float4*)dst)[i] = v;
}

// ---------------- mask canonicalization ----------------
__global__ void mask_convert_kernel(const unsigned char* __restrict__ m) {
    size_t i = (size_t)blockIdx.x * blockDim.x + threadIdx.x;
    if (i >= (size_t)Sq * Sq) return;
    bool is_byte_layout = (m[2048] != 0);
    unsigned char val;
    if (is_byte_layout) val = (m[i] != 0) ? 1 : 0;
    else                val = (((const int*)m)[i] != 0) ? 1 : 0;
    g_mask[i] = val;
}

// ---------------- per-tile union key list + row bitmaps ----------------
__global__ void tile_build_kernel() {
    __shared__ unsigned long long sBits[Sq];
    int tile = blockIdx.x;
    int q0 = tile * QT;
    for (int col = threadIdx.x; col < Sq; col += blockDim.x) {
        unsigned long long bits = 0ULL;
        #pragma unroll 8
        for (int r = 0; r < QT; r++)
            bits |= (unsigned long long)g_mask[(size_t)(q0 + r) * Sq + col] << r;
        sBits[col] = bits;
    }
    __syncthreads();
    if (threadIdx.x == 0) {
        int cnt = 0;
        for (int col = 0; col < Sq; col++) {
            if (sBits[col]) {
                g_tile_idx [(size_t)tile * IDXS_T + cnt] = col;
                g_tile_bits[(size_t)tile * IDXS_T + cnt] = sBits[col];
                cnt++;
            }
        }
        g_tile_cnt[tile] = cnt;
    }
}

// ---------------- layernorm (dual output: exact + tf32-rounded) ----------------
__global__ void ln_kernel(const float* __restrict__ x, const float* __restrict__ g,
                          const float* __restrict__ b, float* __restrict__ out,
                          float* __restrict__ out_r) {
    int row = blockIdx.x;
    const float* xr = x + (size_t)row * Eq;
    float s = 0.f, s2 = 0.f;
    for (int i = threadIdx.x; i < Eq; i += blockDim.x) {
        float v = xr[i];
        s += v; s2 += v * v;
    }
    __shared__ float sh[64];
    #pragma unroll
    for (int o = 16; o; o >>= 1) {
        s  += __shfl_xor_sync(0xffffffffu, s,  o);
        s2 += __shfl_xor_sync(0xffffffffu, s2, o);
    }
    int wid = threadIdx.x >> 5, nl = threadIdx.x & 31;
    if (nl == 0) { sh[wid] = s; sh[32 + wid] = s2; }
    __syncthreads();
    if (wid == 0) {
        int nw = blockDim.x >> 5;
        s  = (nl < nw) ? sh[nl] : 0.f;
        s2 = (nl < nw) ? sh[32 + nl] : 0.f;
        #pragma unroll
        for (int o = 16; o; o >>= 1) {
            s  += __shfl_xor_sync(0xffffffffu, s,  o);
            s2 += __shfl_xor_sync(0xffffffffu, s2, o);
        }
        if (nl == 0) { sh[0] = s; sh[1] = s2; }
    }
    __syncthreads();
    float mean = sh[0] * (1.f / Eq);
    float var  = sh[1] * (1.f / Eq) - mean * mean;
    float rstd = rsqrtf(var + 1e-5f);
    for (int i = threadIdx.x; i < Eq; i += blockDim.x) {
        float v = (xr[i] - mean) * rstd * g[i] + b[i];
        if (out)   out[(size_t)row * Eq + i]   = v;
        if (out_r) out_r[(size_t)row * Eq + i] = f2tf32(v);
    }
}

// ---------------- tf32 tensor-core GEMM: C = epi( A[M,K] @ B[N,K]^T ) ----------------
#define SSTR 36
#define TILEF (128*SSTR)

__global__ __launch_bounds__(256, 2)
void gemm_tf32_kernel(const float* __restrict__ A, const float* __restrict__ Bmat,
                      const float* __restrict__ bias, const float* __restrict__ res,
                      float* __restrict__ C, int M, int N, int K,
                      float alpha, int do_gelu, int round_out)
{
    extern __shared__ float sm[];
    const uint32_t sbase = (uint32_t)__cvta_generic_to_shared(sm);

    int tid = threadIdx.x;
    int bm = blockIdx.y * 128, bn = blockIdx.x * 128;
    int warp = tid >> 5, lane = tid & 31;
    int g = lane >> 2, tig = lane & 3;
    int m0 = (warp >> 1) * 32, n0 = (warp & 1) * 64;

    int lrow = tid >> 1;
    int lcb  = (tid & 1) * 16;
    const float* Ag = A    + (size_t)(bm + lrow) * K + lcb;
    const float* Bg = Bmat + (size_t)(bn + lrow) * K + lcb;
    uint32_t sA_st = sbase + (uint32_t)(lrow * SSTR + lcb) * 4u;

    float acc[2][8][4];
    #pragma unroll
    for (int i = 0; i < 2; i++)
        #pragma unroll
        for (int j = 0; j < 8; j++)
            #pragma unroll
            for (int l = 0; l < 4; l++) acc[i][j][l] = 0.f;

    int T = K / 32;
    {
        #pragma unroll
        for (int j = 0; j < 4; j++) {
            cpa16(sA_st + j * 16, Ag + j * 4);
            cpa16(sA_st + TILEF * 4 + j * 16, Bg + j * 4);
        }
        cp_commit();
    }

    for (int t = 0; t < T; t++) {
        if (t + 1 < T) {
            uint32_t dst = sA_st + (uint32_t)(((t + 1) & 1) * 2 * TILEF) * 4u;
            const float* ap = Ag + (t + 1) * 32;
            const float* bp = Bg + (t + 1) * 32;
            #pragma unroll
            for (int j = 0; j < 4; j++) {
                cpa16(dst + j * 16, ap + j * 4);
                cpa16(dst + TILEF * 4 + j * 16, bp + j * 4);
            }
            cp_commit();
            cp_wait<1>();
        } else {
            cp_wait<0>();
        }
        __syncthreads();

        const float* sA = sm + (t & 1) * 2 * TILEF;
        const float* sB = sA + TILEF;
        #pragma unroll
        for (int ks = 0; ks < 4; ks++) {
            int k = ks * 8;
            uint32_t bfr[8][2];
            #pragma unroll
            for (int nt = 0; nt < 8; nt++) {
                bfr[nt][0] = __float_as_uint(sB[(n0 + nt * 8 + g) * SSTR + k + tig]);
                bfr[nt][1] = __float_as_uint(sB[(n0 + nt * 8 + g) * SSTR + k + tig + 4]);
            }
            #pragma unroll
            for (int mt = 0; mt < 2; mt++) {
                int rbase = (m0 + mt * 16 + g) * SSTR + k;
                uint32_t a0 = __float_as_uint(sA[rbase + tig]);
                uint32_t a1 = __float_as_uint(sA[rbase + 8 * SSTR + tig]);
                uint32_t a2 = __float_as_uint(sA[rbase + tig + 4]);
                uint32_t a3 = __float_as_uint(sA[rbase + 8 * SSTR + tig + 4]);
                #pragma unroll
                for (int nt = 0; nt < 8; nt++)
                    mma1688(acc[mt][nt], a0, a1, a2, a3, bfr[nt][0], bfr[nt][1]);
            }
        }
        __syncthreads();
    }

    const float cgelu = 0.7978845608028654f;
    #pragma unroll
    for (int mt = 0; mt < 2; mt++) {
        #pragma unroll
        for (int half = 0; half < 2; half++) {
            int r = bm + m0 + mt * 16 + g + half * 8;
            #pragma unroll
            for (int nt = 0; nt < 8; nt++) {
                int c = bn + n0 + nt * 8 + 2 * tig;
                float v0 = (acc[mt][nt][half * 2 + 0] + bias[c])     * alpha;
                float v1 = (acc[mt][nt][half * 2 + 1] + bias[c + 1]) * alpha;
                if (do_gelu) {
                    float i0 = cgelu * (v0 + 0.044715f * v0 * v0 * v0);
                    float i1 = cgelu * (v1 + 0.044715f * v1 * v1 * v1);
                    v0 = 0.5f * v0 * (1.f + fast_tanh(i0));
                    v1 = 0.5f * v1 * (1.f + fast_tanh(i1));
                }
                if (res) {
                    v0 += res[(size_t)r * N + c];
                    v1 += res[(size_t)r * N + c + 1];
                }
                if (round_out) { v0 = f2tf32(v0); v1 = f2tf32(v1); }
                *(float2*)(C + (size_t)r * N + c) = make_float2(v0, v1);
            }
        }
    }
}

// ---------------- tiled sparse attention ----------------
// block = (tile, h, b); 256 threads = 8 warps; warp w handles queries [8w, 8w+8)
// within the 64-query tile. Loop over the tile's union key list in chunks of 32,
// staging K/V in smem. lane = key for scoring; lane = dim-pair for accumulation.
__global__ __launch_bounds__(256)
void attn_tile_kernel(const float* __restrict__ q, const float* __restrict__ k,
                      const float* __restrict__ v, float* __restrict__ out)
{
    const float LOG2E = 1.4426950408889634f;
    __shared__ float sQ[QT * 64];
    __shared__ float sK[32 * 65];
    __shared__ float sV[32 * 64];
    __shared__ unsigned long long sBits[32];

    int tile = blockIdx.x, h = blockIdx.y, b = blockIdx.z;
    int q0 = tile * QT;
    int tid = threadIdx.x, warp = tid >> 5, lane = tid & 31;
    int wq0 = warp * 8;

    // load Q tile (64 rows x 64 floats)
    for (int i = tid; i < QT * 16; i += 256) {
        int r = i >> 4, c = (i & 15) * 4;
        float4 f = *(const float4*)(q + (((size_t)b * Sq + q0 + r) * Hn + h) * Dd + c);
        *(float4*)&sQ[r * 64 + c] = f;
    }

    int cnt = g_tile_cnt[tile];
    const int* idx = g_tile_idx + (size_t)tile * IDXS_T;
    const unsigned long long* tb = g_tile_bits + (size_t)tile * IDXS_T;

    float m[8], l[8], acc[8][2];
    #pragma unroll
    for (int qq = 0; qq < 8; qq++) {
        m[qq] = -1e30f; l[qq] = 0.f; acc[qq][0] = 0.f; acc[qq][1] = 0.f;
    }

    for (int c0 = 0; c0 < cnt; c0 += 32) {
        __syncthreads();
        // gather K and V chunk (32 keys x 64 floats each)
        for (int i = tid; i < 32 * 16; i += 256) {
            int j = i >> 4, cc = (i & 15) * 4;
            int kk = (c0 + j < cnt) ? idx[c0 + j] : 0;
            size_t base = (((size_t)b * Sq + kk) * Hn + h) * Dd + cc;
            float4 k4 = *(const float4*)(k + base);
            sK[j * 65 + cc + 0] = k4.x; sK[j * 65 + cc + 1] = k4.y;
            sK[j * 65 + cc + 2] = k4.z; sK[j * 65 + cc + 3] = k4.w;
            *(float4*)&sV[j * 64 + cc] = *(const float4*)(v + base);
        }
        if (tid < 32) sBits[tid] = (c0 + tid < cnt) ? tb[c0 + tid] : 0ULL;
        __syncthreads();

        // scores: lane = key
        float s[8];
        #pragma unroll
        for (int qq = 0; qq < 8; qq++) s[qq] = 0.f;
        #pragma unroll
        for (int dc = 0; dc < 4; dc++) {
            float kr[16];
            #pragma unroll
            for (int ii = 0; ii < 16; ii++) kr[ii] = sK[lane * 65 + dc * 16 + ii];
            #pragma unroll
            for (int qq = 0; qq < 8; qq++) {
                const float* qrow = &sQ[(wq0 + qq) * 64 + dc * 16];
                #pragma unroll
                for (int ii = 0; ii < 16; ii++)
                    s[qq] = fmaf(kr[ii], qrow[ii], s[qq]);
            }
        }

        unsigned long long bits = sBits[lane];
        float p[8];
        #pragma unroll
        for (int qq = 0; qq < 8; qq++) {
            float sv = ((bits >> (wq0 + qq)) & 1ULL) ? s[qq] : -INFINITY;
            float mx = sv;
            #pragma unroll
            for (int o = 16; o; o >>= 1)
                mx = fmaxf(mx, __shfl_xor_sync(0xffffffffu, mx, o));
            float nm = fmaxf(m[qq], mx);
            float cor = fast_ex2((m[qq] - nm) * LOG2E);
            float pv  = fast_ex2((sv - nm) * LOG2E);
            float ls = pv;
            #pragma unroll
            for (int o = 16; o; o >>= 1)
                ls += __shfl_xor_sync(0xffffffffu, ls, o);
            l[qq] = l[qq] * cor + ls;
            m[qq] = nm;
            acc[qq][0] *= cor; acc[qq][1] *= cor;
            p[qq] = pv;
        }

        // P@V: lane = dim pair (2*lane, 2*lane+1)
        #pragma unroll 4
        for (int j = 0; j < 32; j++) {
            float2 vv = *(const float2*)&sV[j * 64 + 2 * lane];
            #pragma unroll
            for (int qq = 0; qq < 8; qq++) {
                float pj = __shfl_sync(0xffffffffu, p[qq], j);
                acc[qq][0] = fmaf(pj, vv.x, acc[qq][0]);
                acc[qq][1] = fmaf(pj, vv.y, acc[qq][1]);
            }
        }
    }

    // epilogue (tf32-rounded for the wo GEMM)
    #pragma unroll
    for (int qq = 0; qq < 8; qq++) {
        float inv = 1.f / l[qq];
        size_t o = (((size_t)b * Sq + q0 + wq0 + qq) * Hn + h) * Dd + 2 * lane;
        *(float2*)(out + o) = make_float2(f2tf32(acc[qq][0] * inv),
                                          f2tf32(acc[qq][1] * inv));
    }
}

// ---------------- host ----------------
extern "C" void kernel_launch(void* const* d_in, const int* in_sizes, int n_in,
                              void* d_out, int out_size) {
    const float* x      = (const float*)d_in[0];
    const float* ln1_g  = (const float*)d_in[1];
    const float* ln1_b  = (const float*)d_in[2];
    const float* ln2_g  = (const float*)d_in[3];
    const float* ln2_b  = (const float*)d_in[4];
    const float* wq     = (const float*)d_in[5];
    const float* bq     = (const float*)d_in[6];
    const float* wk     = (const float*)d_in[7];
    const float* bk     = (const float*)d_in[8];
    const float* wv     = (const float*)d_in[9];
    const float* bv     = (const float*)d_in[10];
    const float* wo     = (const float*)d_in[11];
    const float* bo     = (const float*)d_in[12];
    const float* w_fc   = (const float*)d_in[13];
    const float* b_fc   = (const float*)d_in[14];
    const float* w_proj = (const float*)d_in[15];
    const float* b_proj = (const float*)d_in[16];
    const unsigned char* mask = (const unsigned char*)d_in[17];
    float* out = (float*)d_out;

    float *h, *hr, *qp, *kp, *vp, *attn, *t, *u, *w;
    cudaGetSymbolAddress((void**)&h,    g_h);
    cudaGetSymbolAddress((void**)&hr,   g_hr);
    cudaGetSymbolAddress((void**)&qp,   g_q);
    cudaGetSymbolAddress((void**)&kp,   g_k);
    cudaGetSymbolAddress((void**)&vp,   g_v);
    cudaGetSymbolAddress((void**)&attn, g_attn);
    cudaGetSymbolAddress((void**)&t,    g_t);
    cudaGetSymbolAddress((void**)&u,    g_u);
    cudaGetSymbolAddress((void**)&w,    g_w);

    const size_t EE = (size_t)Eq * Eq;           // 1M
    float* wq_r  = w;
    float* wk_r  = w + EE;
    float* wv_r  = w + 2 * EE;
    float* wo_r  = w + 3 * EE;
    float* wfc_r = w + 4 * EE;
    float* wpr_r = w + 8 * EE;

    const int smem_bytes = 2 * 2 * TILEF * 4;    // 73728
    cudaFuncSetAttribute(gemm_tf32_kernel,
                         cudaFuncAttributeMaxDynamicSharedMemorySize, smem_bytes);

    // 1: fused weight rounding
    round_all_kernel<<<3 * 1024 * 1024 / 256, 256>>>(wq, wk, wv, wo, w_fc, w_proj, w);
    // 2: mask -> canonical uint8
    mask_convert_kernel<<<(int)(((size_t)Sq * Sq + 255) / 256), 256>>>(mask);
    // 3: per-tile union lists + bitmaps
    tile_build_kernel<<<NT, 256>>>();
    // 4: h = ln1(x) (exact + rounded)
    ln_kernel<<<BSq, 256>>>(x, ln1_g, ln1_b, h, hr);

    const float scale = 0.125f; // D^-0.5

    // q,k,v projections (tensor core)
    dim3 gEE(Eq / 128, BSq / 128);
    gemm_tf32_kernel<<<gEE, 256, smem_bytes>>>(hr, wq_r, bq, nullptr, qp, BSq, Eq, Eq, scale, 0, 0);
    gemm_tf32_kernel<<<gEE, 256, smem_bytes>>>(hr, wk_r, bk, nullptr, kp, BSq, Eq, Eq, 1.f, 0, 0);
    gemm_tf32_kernel<<<gEE, 256, smem_bytes>>>(hr, wv_r, bv, nullptr, vp, BSq, Eq, Eq, 1.f, 0, 0);

    // tiled sparse attention
    attn_tile_kernel<<<dim3(NT, Hn, Bq), 256>>>(qp, kp, vp, attn);

    // out = h + attn @ wo^T + bo
    gemm_tf32_kernel<<<gEE, 256, smem_bytes>>>(attn, wo_r, bo, h, out, BSq, Eq, Eq, 1.f, 0, 0);

    // t = ln2(out) (rounded only)
    ln_kernel<<<BSq, 256>>>(out, ln2_g, ln2_b, nullptr, t);

    // u = gelu(t @ w_fc^T + b_fc), rounded
    dim3 gFC(FEq / 128, BSq / 128);
    gemm_tf32_kernel<<<gFC, 256, smem_bytes>>>(t, wfc_r, b_fc, nullptr, u, BSq, FEq, Eq, 1.f, 1, 1);

    // out += u @ w_proj^T + b_proj
    gemm_tf32_kernel<<<gEE, 256, smem_bytes>>>(u, wpr_r, b_proj, out, out, BSq, Eq, FEq, 1.f, 0, 0);
}